// round 2
// baseline (speedup 1.0000x reference)
#include <cuda_runtime.h>
#include <cuda_bf16.h>
#include <cstdint>

// ----------------------------------------------------------------------------
// BitLinear: y = RMSNorm(x) @ w_q^T * gamma
//   x [8192, 4096] f32, w_q [4096, 4096] f32 (ternary), gamma [4096] f32
// Constraint discovered R1: harness PTX target is baseline sm_103 (no 'a'),
// so NO tcgen05/TMEM. Use Ampere-style mma.sync bf16 pipeline instead.
// Precision: split bf16 (hi+lo) double pass into one fp32 accumulator.
// ----------------------------------------------------------------------------

#define DIN   4096
#define DOUT  4096
#define MROWS 8192

// scratch (allocation-free rule: __device__ globals)
__device__ __align__(256) __nv_bfloat16 g_xhi[(size_t)MROWS * DIN];
__device__ __align__(256) __nv_bfloat16 g_xlo[(size_t)MROWS * DIN];
__device__ __align__(256) __nv_bfloat16 g_wq [(size_t)DOUT * DIN];

// ---------------------------- PTX helpers -----------------------------------
__device__ __forceinline__ uint32_t smem_u32(const void* p) {
    uint32_t a;
    asm("{ .reg .u64 t; cvta.to.shared.u64 t, %1; cvt.u32.u64 %0, t; }"
        : "=r"(a) : "l"(p));
    return a;
}

__device__ __forceinline__ void cp_async16(uint32_t dst, const void* src) {
    asm volatile("cp.async.cg.shared.global [%0], [%1], 16;"
                 :: "r"(dst), "l"(src));
}

#define CP_COMMIT() asm volatile("cp.async.commit_group;" ::: "memory")

#define LDSM_X4(r0, r1, r2, r3, addr) \
    asm volatile("ldmatrix.sync.aligned.m8n8.x4.shared.b16 {%0,%1,%2,%3}, [%4];" \
                 : "=r"(r0), "=r"(r1), "=r"(r2), "=r"(r3) : "r"(addr))

#define MMA16816(d, a, b0, b1) \
    asm volatile("mma.sync.aligned.m16n8k16.row.col.f32.bf16.bf16.f32 " \
                 "{%0,%1,%2,%3}, {%4,%5,%6,%7}, {%8,%9}, {%0,%1,%2,%3};" \
                 : "+f"((d)[0]), "+f"((d)[1]), "+f"((d)[2]), "+f"((d)[3]) \
                 : "r"((a)[0]), "r"((a)[1]), "r"((a)[2]), "r"((a)[3]), \
                   "r"(b0), "r"(b1))

// ----------------------------- GEMM config ----------------------------------
constexpr int BM = 128, BN = 128, BK = 64;
constexpr int KTILES = DIN / BK;              // 64
constexpr int STAGES = 4;
constexpr int TILE_B  = BM * BK * 2;          // 16384 B per bf16 tile
constexpr int STAGE_B = 3 * TILE_B;           // A_hi + A_lo + B = 49152
constexpr int SMEM_SZ = STAGES * STAGE_B;     // 196608

// ------------------------ Kernel 1: RMSNorm + split -------------------------
__global__ __launch_bounds__(256) void rmsnorm_split_kernel(
    const float* __restrict__ x, const float* __restrict__ nw) {
    const int row = blockIdx.x;
    const float4* xr = reinterpret_cast<const float4*>(x) + (size_t)row * (DIN / 4);
    const float4* nw4 = reinterpret_cast<const float4*>(nw);
    const int t = threadIdx.x;

    float4 v[4];
    float ss = 0.f;
#pragma unroll
    for (int i = 0; i < 4; i++) {
        v[i] = xr[t + i * 256];
        ss += v[i].x * v[i].x + v[i].y * v[i].y + v[i].z * v[i].z + v[i].w * v[i].w;
    }
#pragma unroll
    for (int o = 16; o > 0; o >>= 1) ss += __shfl_xor_sync(0xffffffffu, ss, o);

    __shared__ float wss[8];
    __shared__ float s_scale;
    if ((t & 31) == 0) wss[t >> 5] = ss;
    __syncthreads();
    if (t == 0) {
        float tot = 0.f;
#pragma unroll
        for (int i = 0; i < 8; i++) tot += wss[i];
        s_scale = rsqrtf(tot * (1.0f / DIN) + 1e-6f);
    }
    __syncthreads();
    const float sc = s_scale;

    uint2* hi = reinterpret_cast<uint2*>(g_xhi + (size_t)row * DIN);
    uint2* lo = reinterpret_cast<uint2*>(g_xlo + (size_t)row * DIN);
#pragma unroll
    for (int i = 0; i < 4; i++) {
        float4 w = nw4[t + i * 256];
        float a0 = v[i].x * sc * w.x;
        float a1 = v[i].y * sc * w.y;
        float a2 = v[i].z * sc * w.z;
        float a3 = v[i].w * sc * w.w;
        __nv_bfloat162 h01 = __floats2bfloat162_rn(a0, a1);
        __nv_bfloat162 h23 = __floats2bfloat162_rn(a2, a3);
        __nv_bfloat162 l01 = __floats2bfloat162_rn(a0 - __bfloat162float(h01.x),
                                                   a1 - __bfloat162float(h01.y));
        __nv_bfloat162 l23 = __floats2bfloat162_rn(a2 - __bfloat162float(h23.x),
                                                   a3 - __bfloat162float(h23.y));
        uint2 uh, ul;
        uh.x = *reinterpret_cast<uint32_t*>(&h01);
        uh.y = *reinterpret_cast<uint32_t*>(&h23);
        ul.x = *reinterpret_cast<uint32_t*>(&l01);
        ul.y = *reinterpret_cast<uint32_t*>(&l23);
        hi[t + i * 256] = uh;
        lo[t + i * 256] = ul;
    }
}

// ------------------------ Kernel 2: w_q fp32 -> bf16 -------------------------
__global__ __launch_bounds__(256) void wconv_kernel(const float* __restrict__ w) {
    const size_t gid = (size_t)blockIdx.x * 256 + threadIdx.x;
    const float4* w4 = reinterpret_cast<const float4*>(w);
    uint2* o = reinterpret_cast<uint2*>(g_wq);
#pragma unroll
    for (int i = 0; i < 4; i++) {
        size_t idx = gid + (size_t)i * 1048576;
        float4 v = w4[idx];
        __nv_bfloat162 h01 = __floats2bfloat162_rn(v.x, v.y);
        __nv_bfloat162 h23 = __floats2bfloat162_rn(v.z, v.w);
        uint2 u;
        u.x = *reinterpret_cast<uint32_t*>(&h01);
        u.y = *reinterpret_cast<uint32_t*>(&h23);
        o[idx] = u;
    }
}

// ------------------------ Kernel 3: HMMA GEMM --------------------------------
// 256 threads = 8 warps in a 4(m) x 2(n) grid; warp tile 32x64.
// Per BK=64 stage: 4 k16-steps; per step 8 ldmatrix.x4 + 32 HMMA (hi+lo share B).
__global__ __launch_bounds__(256, 1)
void bitlinear_gemm_kernel(const float* __restrict__ gamma, float* __restrict__ out) {
    extern __shared__ char smem[];
    const uint32_t sb = smem_u32(smem);
    const int tid = threadIdx.x;
    const int wid = tid >> 5;
    const int lane = tid & 31;
    const int warp_m = wid >> 1;       // 0..3
    const int warp_n = wid & 1;        // 0..1
    const int m0 = blockIdx.y * BM;
    const int n0 = blockIdx.x * BN;

    // ---- per-thread copy geometry (same for all 3 tiles; rows differ by base)
    // 1024 16B-chunks per tile, 256 threads -> 4 chunks/thread.
    const int cc = tid & 7;                 // 16B col 0..7 (constant per thread)
    uint32_t soff[4];
    uint32_t grow[4];
#pragma unroll
    for (int i = 0; i < 4; i++) {
        int r = i * 32 + (tid >> 3);        // row 0..127
        soff[i] = (uint32_t)(r * 128 + ((cc ^ (r & 7)) << 4));
        grow[i] = (uint32_t)r;
    }
    const char* gA = (const char*)g_xhi + (size_t)m0 * (DIN * 2);
    const char* gL = (const char*)g_xlo + (size_t)m0 * (DIN * 2);
    const char* gB = (const char*)g_wq  + (size_t)n0 * (DIN * 2);

    auto issue_stage = [&](int s, int kt) {
        const uint32_t sdst = sb + (uint32_t)s * STAGE_B;
        const uint32_t koff = (uint32_t)kt * 128 + (uint32_t)cc * 16;
#pragma unroll
        for (int i = 0; i < 4; i++) {
            const size_t go = (size_t)grow[i] * (DIN * 2) + koff;
            cp_async16(sdst + soff[i],              gA + go);
            cp_async16(sdst + TILE_B + soff[i],     gL + go);
            cp_async16(sdst + 2 * TILE_B + soff[i], gB + go);
        }
    };

    // ---- ldmatrix address components
    // A (hi/lo): 16x16 frag; lanes 0-15 rows, lanes 16-31 k-half.
    const int rA0 = warp_m * 32 + (lane & 15);          // mi=0 row
    const int cgA = lane >> 4;                          // 0/1 k 16B-half
    // B: x4 over n16: groups g=lane>>3: (n0-7,klo),(n0-7,khi),(n8-15,klo),(n8-15,khi)
    const int gB4 = lane >> 3;
    const int rB0 = warp_n * 64 + ((gB4 & 2) << 2) + (lane & 7);  // p=0 row
    const int cgB = gB4 & 1;

    float acc[2][8][4];
#pragma unroll
    for (int mi = 0; mi < 2; mi++)
#pragma unroll
        for (int nj = 0; nj < 8; nj++)
#pragma unroll
            for (int e = 0; e < 4; e++) acc[mi][nj][e] = 0.f;

    // ---- prologue: fill 3 stages
#pragma unroll
    for (int s = 0; s < STAGES - 1; s++) { issue_stage(s, s); CP_COMMIT(); }

    // ---- main loop
    for (int kt = 0; kt < KTILES; kt++) {
        asm volatile("cp.async.wait_group 2;" ::: "memory");
        __syncthreads();

        const int nk = kt + STAGES - 1;
        if (nk < KTILES) issue_stage(nk & (STAGES - 1), nk);
        CP_COMMIT();

        const uint32_t base = sb + (uint32_t)(kt & (STAGES - 1)) * STAGE_B;

#pragma unroll
        for (int kk = 0; kk < 4; kk++) {
            uint32_t ah[2][4], al[2][4], bf[4][4];
            // A hi + lo
#pragma unroll
            for (int mi = 0; mi < 2; mi++) {
                const int r = rA0 + mi * 16;
                const uint32_t off =
                    (uint32_t)(r * 128 + (((kk * 2 + cgA) ^ (r & 7)) << 4));
                LDSM_X4(ah[mi][0], ah[mi][1], ah[mi][2], ah[mi][3], base + off);
                LDSM_X4(al[mi][0], al[mi][1], al[mi][2], al[mi][3],
                        base + TILE_B + off);
            }
            // B (shared by both passes)
#pragma unroll
            for (int p = 0; p < 4; p++) {
                const int r = rB0 + p * 16;
                const uint32_t off =
                    (uint32_t)(r * 128 + (((kk * 2 + cgB) ^ (r & 7)) << 4));
                LDSM_X4(bf[p][0], bf[p][1], bf[p][2], bf[p][3],
                        base + 2 * TILE_B + off);
            }
            // hi pass
#pragma unroll
            for (int mi = 0; mi < 2; mi++)
#pragma unroll
                for (int p = 0; p < 4; p++) {
                    MMA16816(acc[mi][2 * p],     ah[mi], bf[p][0], bf[p][1]);
                    MMA16816(acc[mi][2 * p + 1], ah[mi], bf[p][2], bf[p][3]);
                }
            // lo pass
#pragma unroll
            for (int mi = 0; mi < 2; mi++)
#pragma unroll
                for (int p = 0; p < 4; p++) {
                    MMA16816(acc[mi][2 * p],     al[mi], bf[p][0], bf[p][1]);
                    MMA16816(acc[mi][2 * p + 1], al[mi], bf[p][2], bf[p][3]);
                }
        }
    }

    // ---- epilogue: *gamma, write f32
    const int col_l = (lane & 3) * 2;
    const float* gptr = gamma + n0 + warp_n * 64;
    float gv0[8], gv1[8];
#pragma unroll
    for (int nj = 0; nj < 8; nj++) {
        gv0[nj] = __ldg(gptr + nj * 8 + col_l);
        gv1[nj] = __ldg(gptr + nj * 8 + col_l + 1);
    }

    const int row_base = m0 + warp_m * 32 + (lane >> 2);
#pragma unroll
    for (int mi = 0; mi < 2; mi++) {
        float* op0 = out + (size_t)(row_base + mi * 16) * DOUT + n0 + warp_n * 64;
        float* op1 = op0 + (size_t)8 * DOUT;
#pragma unroll
        for (int nj = 0; nj < 8; nj++) {
            float2 v0, v1;
            v0.x = acc[mi][nj][0] * gv0[nj];
            v0.y = acc[mi][nj][1] * gv1[nj];
            v1.x = acc[mi][nj][2] * gv0[nj];
            v1.y = acc[mi][nj][3] * gv1[nj];
            *reinterpret_cast<float2*>(op0 + nj * 8 + col_l) = v0;
            *reinterpret_cast<float2*>(op1 + nj * 8 + col_l) = v1;
        }
    }
}

// ------------------------------- launch --------------------------------------
extern "C" void kernel_launch(void* const* d_in, const int* in_sizes, int n_in,
                              void* d_out, int out_size) {
    const float* x     = (const float*)d_in[0];  // [2,4096,4096]
    const float* nw    = (const float*)d_in[1];  // [4096]
    const float* wq    = (const float*)d_in[2];  // [4096,4096]
    const float* gamma = (const float*)d_in[3];  // [4096]
    float* out = (float*)d_out;

    cudaFuncSetAttribute(bitlinear_gemm_kernel,
                         cudaFuncAttributeMaxDynamicSharedMemorySize, SMEM_SZ);

    rmsnorm_split_kernel<<<MROWS, 256>>>(x, nw);
    wconv_kernel<<<4096, 256>>>(wq);
    bitlinear_gemm_kernel<<<dim3(DOUT / BN, MROWS / BM), 256, SMEM_SZ>>>(gamma, out);
}

// round 3
// speedup vs baseline: 1.6902x; 1.6902x over previous
#include <cuda_runtime.h>
#include <cuda_fp16.h>
#include <cstdint>

// ----------------------------------------------------------------------------
// BitLinear: y = RMSNorm(x) @ w_q^T * gamma
//   x [8192, 4096] f32, w_q [4096, 4096] f32 (ternary), gamma [4096] f32
// R1 finding: harness PTX target is baseline sm_103 (no 'a') -> no tcgen05.
// R2 finding: two-pass bf16 gave rel_err 5.5e-6 (180x under gate) @ 1306us.
// R3: single-pass fp16 HMMA (rel_err ~2.5e-4, still 4x under gate), half the
//     MMA work, smaller smem stages, half the xn scratch traffic.
// ----------------------------------------------------------------------------

#define DIN   4096
#define DOUT  4096
#define MROWS 8192

// scratch (allocation-free rule: __device__ globals)
__device__ __align__(256) __half g_xn[(size_t)MROWS * DIN];
__device__ __align__(256) __half g_wq[(size_t)DOUT * DIN];

// ---------------------------- PTX helpers -----------------------------------
__device__ __forceinline__ uint32_t smem_u32(const void* p) {
    uint32_t a;
    asm("{ .reg .u64 t; cvta.to.shared.u64 t, %1; cvt.u32.u64 %0, t; }"
        : "=r"(a) : "l"(p));
    return a;
}

__device__ __forceinline__ void cp_async16(uint32_t dst, const void* src) {
    asm volatile("cp.async.cg.shared.global [%0], [%1], 16;"
                 :: "r"(dst), "l"(src));
}

#define CP_COMMIT() asm volatile("cp.async.commit_group;" ::: "memory")

#define LDSM_X4(r0, r1, r2, r3, addr) \
    asm volatile("ldmatrix.sync.aligned.m8n8.x4.shared.b16 {%0,%1,%2,%3}, [%4];" \
                 : "=r"(r0), "=r"(r1), "=r"(r2), "=r"(r3) : "r"(addr))

#define MMA16816(d, a, b0, b1) \
    asm volatile("mma.sync.aligned.m16n8k16.row.col.f32.f16.f16.f32 " \
                 "{%0,%1,%2,%3}, {%4,%5,%6,%7}, {%8,%9}, {%0,%1,%2,%3};" \
                 : "+f"((d)[0]), "+f"((d)[1]), "+f"((d)[2]), "+f"((d)[3]) \
                 : "r"((a)[0]), "r"((a)[1]), "r"((a)[2]), "r"((a)[3]), \
                   "r"(b0), "r"(b1))

// ----------------------------- GEMM config ----------------------------------
constexpr int BM = 128, BN = 128, BK = 64;
constexpr int KTILES = DIN / BK;              // 64
constexpr int STAGES = 4;
constexpr int TILE_B  = BM * BK * 2;          // 16384 B per fp16 tile
constexpr int STAGE_B = 2 * TILE_B;           // A + B = 32768
constexpr int SMEM_SZ = STAGES * STAGE_B;     // 131072

// ------------------------ Kernel 1: RMSNorm -> fp16 --------------------------
__global__ __launch_bounds__(256) void rmsnorm_kernel(
    const float* __restrict__ x, const float* __restrict__ nw) {
    const int row = blockIdx.x;
    const float4* xr = reinterpret_cast<const float4*>(x) + (size_t)row * (DIN / 4);
    const float4* nw4 = reinterpret_cast<const float4*>(nw);
    const int t = threadIdx.x;

    float4 v[4];
    float ss = 0.f;
#pragma unroll
    for (int i = 0; i < 4; i++) {
        v[i] = xr[t + i * 256];
        ss += v[i].x * v[i].x + v[i].y * v[i].y + v[i].z * v[i].z + v[i].w * v[i].w;
    }
#pragma unroll
    for (int o = 16; o > 0; o >>= 1) ss += __shfl_xor_sync(0xffffffffu, ss, o);

    __shared__ float wss[8];
    __shared__ float s_scale;
    if ((t & 31) == 0) wss[t >> 5] = ss;
    __syncthreads();
    if (t == 0) {
        float tot = 0.f;
#pragma unroll
        for (int i = 0; i < 8; i++) tot += wss[i];
        s_scale = rsqrtf(tot * (1.0f / DIN) + 1e-6f);
    }
    __syncthreads();
    const float sc = s_scale;

    uint2* xo = reinterpret_cast<uint2*>(g_xn + (size_t)row * DIN);
#pragma unroll
    for (int i = 0; i < 4; i++) {
        float4 w = nw4[t + i * 256];
        __half2 h01 = __floats2half2_rn(v[i].x * sc * w.x, v[i].y * sc * w.y);
        __half2 h23 = __floats2half2_rn(v[i].z * sc * w.z, v[i].w * sc * w.w);
        uint2 u;
        u.x = *reinterpret_cast<uint32_t*>(&h01);
        u.y = *reinterpret_cast<uint32_t*>(&h23);
        xo[t + i * 256] = u;
    }
}

// ------------------------ Kernel 2: w_q fp32 -> fp16 --------------------------
__global__ __launch_bounds__(256) void wconv_kernel(const float* __restrict__ w) {
    const size_t gid = (size_t)blockIdx.x * 256 + threadIdx.x;
    const float4* w4 = reinterpret_cast<const float4*>(w);
    uint2* o = reinterpret_cast<uint2*>(g_wq);
#pragma unroll
    for (int i = 0; i < 4; i++) {
        size_t idx = gid + (size_t)i * 1048576;
        float4 v = w4[idx];
        __half2 h01 = __floats2half2_rn(v.x, v.y);
        __half2 h23 = __floats2half2_rn(v.z, v.w);
        uint2 u;
        u.x = *reinterpret_cast<uint32_t*>(&h01);
        u.y = *reinterpret_cast<uint32_t*>(&h23);
        o[idx] = u;
    }
}

// ------------------------ Kernel 3: HMMA GEMM --------------------------------
// 256 threads = 8 warps in a 4(m) x 2(n) grid; warp tile 32x64.
// Per BK=64 stage: 4 k16-steps; per step 6 ldmatrix.x4 + 16 HMMA.
__global__ __launch_bounds__(256, 1)
void bitlinear_gemm_kernel(const float* __restrict__ gamma, float* __restrict__ out) {
    extern __shared__ char smem[];
    const uint32_t sb = smem_u32(smem);
    const int tid = threadIdx.x;
    const int wid = tid >> 5;
    const int lane = tid & 31;
    const int warp_m = wid >> 1;       // 0..3
    const int warp_n = wid & 1;        // 0..1
    const int m0 = blockIdx.y * BM;
    const int n0 = blockIdx.x * BN;

    // ---- per-thread copy geometry: 1024 16B-chunks/tile, 4 chunks/thread
    const int cc = tid & 7;                 // 16B col 0..7
    uint32_t soff[4];
    uint32_t grow[4];
#pragma unroll
    for (int i = 0; i < 4; i++) {
        int r = i * 32 + (tid >> 3);        // row 0..127
        soff[i] = (uint32_t)(r * 128 + ((cc ^ (r & 7)) << 4));
        grow[i] = (uint32_t)r;
    }
    const char* gA = (const char*)g_xn + (size_t)m0 * (DIN * 2);
    const char* gB = (const char*)g_wq + (size_t)n0 * (DIN * 2);

    auto issue_stage = [&](int s, int kt) {
        const uint32_t sdst = sb + (uint32_t)s * STAGE_B;
        const uint32_t koff = (uint32_t)kt * 128 + (uint32_t)cc * 16;
#pragma unroll
        for (int i = 0; i < 4; i++) {
            const size_t go = (size_t)grow[i] * (DIN * 2) + koff;
            cp_async16(sdst + soff[i],          gA + go);
            cp_async16(sdst + TILE_B + soff[i], gB + go);
        }
    };

    // ---- ldmatrix address components
    const int rA0 = warp_m * 32 + (lane & 15);          // A: mi=0 row
    const int cgA = lane >> 4;                          // A: k 16B-half
    const int gB4 = lane >> 3;                          // B groups
    const int rB0 = warp_n * 64 + ((gB4 & 2) << 2) + (lane & 7);
    const int cgB = gB4 & 1;

    float acc[2][8][4];
#pragma unroll
    for (int mi = 0; mi < 2; mi++)
#pragma unroll
        for (int nj = 0; nj < 8; nj++)
#pragma unroll
            for (int e = 0; e < 4; e++) acc[mi][nj][e] = 0.f;

    // ---- prologue: fill 3 stages
#pragma unroll
    for (int s = 0; s < STAGES - 1; s++) { issue_stage(s, s); CP_COMMIT(); }

    // ---- main loop
    for (int kt = 0; kt < KTILES; kt++) {
        asm volatile("cp.async.wait_group 2;" ::: "memory");
        __syncthreads();

        const int nk = kt + STAGES - 1;
        if (nk < KTILES) issue_stage(nk & (STAGES - 1), nk);
        CP_COMMIT();

        const uint32_t base = sb + (uint32_t)(kt & (STAGES - 1)) * STAGE_B;

#pragma unroll
        for (int kk = 0; kk < 4; kk++) {
            uint32_t ah[2][4], bf[4][4];
#pragma unroll
            for (int mi = 0; mi < 2; mi++) {
                const int r = rA0 + mi * 16;
                const uint32_t off =
                    (uint32_t)(r * 128 + (((kk * 2 + cgA) ^ (r & 7)) << 4));
                LDSM_X4(ah[mi][0], ah[mi][1], ah[mi][2], ah[mi][3], base + off);
            }
#pragma unroll
            for (int p = 0; p < 4; p++) {
                const int r = rB0 + p * 16;
                const uint32_t off =
                    (uint32_t)(r * 128 + (((kk * 2 + cgB) ^ (r & 7)) << 4));
                LDSM_X4(bf[p][0], bf[p][1], bf[p][2], bf[p][3],
                        base + TILE_B + off);
            }
#pragma unroll
            for (int mi = 0; mi < 2; mi++)
#pragma unroll
                for (int p = 0; p < 4; p++) {
                    MMA16816(acc[mi][2 * p],     ah[mi], bf[p][0], bf[p][1]);
                    MMA16816(acc[mi][2 * p + 1], ah[mi], bf[p][2], bf[p][3]);
                }
        }
    }

    // ---- epilogue: *gamma, write f32
    const int col_l = (lane & 3) * 2;
    const float* gptr = gamma + n0 + warp_n * 64;
    float gv0[8], gv1[8];
#pragma unroll
    for (int nj = 0; nj < 8; nj++) {
        gv0[nj] = __ldg(gptr + nj * 8 + col_l);
        gv1[nj] = __ldg(gptr + nj * 8 + col_l + 1);
    }

    const int row_base = m0 + warp_m * 32 + (lane >> 2);
#pragma unroll
    for (int mi = 0; mi < 2; mi++) {
        float* op0 = out + (size_t)(row_base + mi * 16) * DOUT + n0 + warp_n * 64;
        float* op1 = op0 + (size_t)8 * DOUT;
#pragma unroll
        for (int nj = 0; nj < 8; nj++) {
            float2 v0, v1;
            v0.x = acc[mi][nj][0] * gv0[nj];
            v0.y = acc[mi][nj][1] * gv1[nj];
            v1.x = acc[mi][nj][2] * gv0[nj];
            v1.y = acc[mi][nj][3] * gv1[nj];
            *reinterpret_cast<float2*>(op0 + nj * 8 + col_l) = v0;
            *reinterpret_cast<float2*>(op1 + nj * 8 + col_l) = v1;
        }
    }
}

// ------------------------------- launch --------------------------------------
extern "C" void kernel_launch(void* const* d_in, const int* in_sizes, int n_in,
                              void* d_out, int out_size) {
    const float* x     = (const float*)d_in[0];  // [2,4096,4096]
    const float* nw    = (const float*)d_in[1];  // [4096]
    const float* wq    = (const float*)d_in[2];  // [4096,4096]
    const float* gamma = (const float*)d_in[3];  // [4096]
    float* out = (float*)d_out;

    cudaFuncSetAttribute(bitlinear_gemm_kernel,
                         cudaFuncAttributeMaxDynamicSharedMemorySize, SMEM_SZ);

    rmsnorm_kernel<<<MROWS, 256>>>(x, nw);
    wconv_kernel<<<4096, 256>>>(wq);
    bitlinear_gemm_kernel<<<dim3(DOUT / BN, MROWS / BM), 256, SMEM_SZ>>>(gamma, out);
}

// round 4
// speedup vs baseline: 1.8752x; 1.1094x over previous
#include <cuda_runtime.h>
#include <cuda_fp16.h>
#include <cstdint>

// ----------------------------------------------------------------------------
// BitLinear: y = RMSNorm(x) @ w_q^T * gamma
// R1: harness PTX target is baseline sm_103 (no 'a') -> no tcgen05.
// R2: two-pass bf16 @1306us, rel_err 5.5e-6 (over-precise).
// R3: single-pass fp16 @773us, rel_err 2.1e-4. 12.1 cyc/HMMA vs ~8 floor.
// R4: warp tile 64x64 (CTA 128x256), HMMA:LDSM 4:1, halve loop overhead.
// ----------------------------------------------------------------------------

#define DIN   4096
#define DOUT  4096
#define MROWS 8192

__device__ __align__(256) __half g_xn[(size_t)MROWS * DIN];
__device__ __align__(256) __half g_wq[(size_t)DOUT * DIN];

// ---------------------------- PTX helpers -----------------------------------
__device__ __forceinline__ uint32_t smem_u32(const void* p) {
    uint32_t a;
    asm("{ .reg .u64 t; cvta.to.shared.u64 t, %1; cvt.u32.u64 %0, t; }"
        : "=r"(a) : "l"(p));
    return a;
}

__device__ __forceinline__ void cp_async16(uint32_t dst, const void* src) {
    asm volatile("cp.async.cg.shared.global [%0], [%1], 16;"
                 :: "r"(dst), "l"(src));
}

#define CP_COMMIT() asm volatile("cp.async.commit_group;" ::: "memory")

#define LDSM_X4(r0, r1, r2, r3, addr) \
    asm volatile("ldmatrix.sync.aligned.m8n8.x4.shared.b16 {%0,%1,%2,%3}, [%4];" \
                 : "=r"(r0), "=r"(r1), "=r"(r2), "=r"(r3) : "r"(addr))

#define MMA16816(d, a, b0, b1) \
    asm volatile("mma.sync.aligned.m16n8k16.row.col.f32.f16.f16.f32 " \
                 "{%0,%1,%2,%3}, {%4,%5,%6,%7}, {%8,%9}, {%0,%1,%2,%3};" \
                 : "+f"((d)[0]), "+f"((d)[1]), "+f"((d)[2]), "+f"((d)[3]) \
                 : "r"((a)[0]), "r"((a)[1]), "r"((a)[2]), "r"((a)[3]), \
                   "r"(b0), "r"(b1))

// ----------------------------- GEMM config ----------------------------------
constexpr int BM = 128, BN = 256, BK = 64;
constexpr int KTILES = DIN / BK;               // 64
constexpr int STAGES = 4;
constexpr int TILE_A  = BM * BK * 2;           // 16384 B
constexpr int TILE_BB = BN * BK * 2;           // 32768 B
constexpr int STAGE_B = TILE_A + TILE_BB;      // 49152
constexpr int SMEM_SZ = STAGES * STAGE_B;      // 196608

// ------------------------ Kernel 1: RMSNorm -> fp16 --------------------------
__global__ __launch_bounds__(256) void rmsnorm_kernel(
    const float* __restrict__ x, const float* __restrict__ nw) {
    const int row = blockIdx.x;
    const float4* xr = reinterpret_cast<const float4*>(x) + (size_t)row * (DIN / 4);
    const float4* nw4 = reinterpret_cast<const float4*>(nw);
    const int t = threadIdx.x;

    float4 v[4];
    float ss = 0.f;
#pragma unroll
    for (int i = 0; i < 4; i++) {
        v[i] = xr[t + i * 256];
        ss += v[i].x * v[i].x + v[i].y * v[i].y + v[i].z * v[i].z + v[i].w * v[i].w;
    }
#pragma unroll
    for (int o = 16; o > 0; o >>= 1) ss += __shfl_xor_sync(0xffffffffu, ss, o);

    __shared__ float wss[8];
    __shared__ float s_scale;
    if ((t & 31) == 0) wss[t >> 5] = ss;
    __syncthreads();
    if (t == 0) {
        float tot = 0.f;
#pragma unroll
        for (int i = 0; i < 8; i++) tot += wss[i];
        s_scale = rsqrtf(tot * (1.0f / DIN) + 1e-6f);
    }
    __syncthreads();
    const float sc = s_scale;

    uint2* xo = reinterpret_cast<uint2*>(g_xn + (size_t)row * DIN);
#pragma unroll
    for (int i = 0; i < 4; i++) {
        float4 w = nw4[t + i * 256];
        __half2 h01 = __floats2half2_rn(v[i].x * sc * w.x, v[i].y * sc * w.y);
        __half2 h23 = __floats2half2_rn(v[i].z * sc * w.z, v[i].w * sc * w.w);
        uint2 u;
        u.x = *reinterpret_cast<uint32_t*>(&h01);
        u.y = *reinterpret_cast<uint32_t*>(&h23);
        xo[t + i * 256] = u;
    }
}

// ------------------------ Kernel 2: w_q fp32 -> fp16 --------------------------
__global__ __launch_bounds__(256) void wconv_kernel(const float* __restrict__ w) {
    const size_t gid = (size_t)blockIdx.x * 256 + threadIdx.x;
    const float4* w4 = reinterpret_cast<const float4*>(w);
    uint2* o = reinterpret_cast<uint2*>(g_wq);
#pragma unroll
    for (int i = 0; i < 4; i++) {
        size_t idx = gid + (size_t)i * 1048576;
        float4 v = w4[idx];
        __half2 h01 = __floats2half2_rn(v.x, v.y);
        __half2 h23 = __floats2half2_rn(v.z, v.w);
        uint2 u;
        u.x = *reinterpret_cast<uint32_t*>(&h01);
        u.y = *reinterpret_cast<uint32_t*>(&h23);
        o[idx] = u;
    }
}

// ------------------------ Kernel 3: HMMA GEMM --------------------------------
// 256 threads = 8 warps in a 2(m) x 4(n) grid; warp tile 64x64.
// Per k16-step per warp: 8 ldmatrix.x4 + 32 HMMA (1:4).
__global__ __launch_bounds__(256, 1)
void bitlinear_gemm_kernel(const float* __restrict__ gamma, float* __restrict__ out) {
    extern __shared__ char smem[];
    const uint32_t sb = smem_u32(smem);
    const int tid = threadIdx.x;
    const int wid = tid >> 5;
    const int lane = tid & 31;
    const int warp_m = wid >> 2;       // 0..1
    const int warp_n = wid & 3;        // 0..3
    const int m0 = blockIdx.y * BM;
    const int n0 = blockIdx.x * BN;

    // ---- per-thread copy geometry (16B chunks; 128B rows, XOR swizzle)
    const int cc = tid & 7;                    // 16B col 0..7
    const int r0c = tid >> 3;                  // base row 0..31
    const uint32_t so_base = (uint32_t)(r0c * 128 + ((cc ^ (r0c & 7)) << 4));
    // row += 32 flips no swizzle bits (r&7 invariant) -> just +32*128 bytes
    const char* gA = (const char*)g_xn + (size_t)m0 * (DIN * 2);
    const char* gB = (const char*)g_wq + (size_t)n0 * (DIN * 2);
    const size_t grow0 = (size_t)r0c * (DIN * 2);

    auto issue_stage = [&](int s, int kt) {
        const uint32_t sdst = sb + (uint32_t)s * STAGE_B;
        const uint32_t koff = (uint32_t)kt * 128 + (uint32_t)cc * 16;
        const char* a = gA + grow0 + koff;
        const char* b = gB + grow0 + koff;
#pragma unroll
        for (int i = 0; i < 4; i++)   // A: 128 rows
            cp_async16(sdst + so_base + i * (32 * 128),
                       a + (size_t)i * (32 * DIN * 2));
#pragma unroll
        for (int i = 0; i < 8; i++)   // B: 256 rows
            cp_async16(sdst + TILE_A + so_base + i * (32 * 128),
                       b + (size_t)i * (32 * DIN * 2));
    };

    // ---- ldmatrix address components
    const int rA0 = warp_m * 64 + (lane & 15);           // A frag row (mi=0)
    const int cgA = lane >> 4;                           // A k 16B-half
    const int gB4 = lane >> 3;
    const int rB0 = warp_n * 64 + ((gB4 & 2) << 2) + (lane & 7);
    const int cgB = gB4 & 1;

    float acc[4][8][4];
#pragma unroll
    for (int mi = 0; mi < 4; mi++)
#pragma unroll
        for (int nj = 0; nj < 8; nj++)
#pragma unroll
            for (int e = 0; e < 4; e++) acc[mi][nj][e] = 0.f;

    // ---- prologue
#pragma unroll
    for (int s = 0; s < STAGES - 1; s++) { issue_stage(s, s); CP_COMMIT(); }

    // ---- main loop
    for (int kt = 0; kt < KTILES; kt++) {
        asm volatile("cp.async.wait_group 2;" ::: "memory");
        __syncthreads();

        const int nk = kt + STAGES - 1;
        if (nk < KTILES) issue_stage(nk & (STAGES - 1), nk);
        CP_COMMIT();

        const uint32_t base = sb + (uint32_t)(kt & (STAGES - 1)) * STAGE_B;

#pragma unroll
        for (int kk = 0; kk < 4; kk++) {
            uint32_t af[4][4], bf[4][4];
#pragma unroll
            for (int mi = 0; mi < 4; mi++) {
                const int r = rA0 + mi * 16;
                const uint32_t off =
                    (uint32_t)(r * 128 + (((kk * 2 + cgA) ^ (r & 7)) << 4));
                LDSM_X4(af[mi][0], af[mi][1], af[mi][2], af[mi][3], base + off);
            }
#pragma unroll
            for (int p = 0; p < 4; p++) {
                const int r = rB0 + p * 16;
                const uint32_t off =
                    (uint32_t)(r * 128 + (((kk * 2 + cgB) ^ (r & 7)) << 4));
                LDSM_X4(bf[p][0], bf[p][1], bf[p][2], bf[p][3],
                        base + TILE_A + off);
            }
#pragma unroll
            for (int mi = 0; mi < 4; mi++)
#pragma unroll
                for (int p = 0; p < 4; p++) {
                    MMA16816(acc[mi][2 * p],     af[mi], bf[p][0], bf[p][1]);
                    MMA16816(acc[mi][2 * p + 1], af[mi], bf[p][2], bf[p][3]);
                }
        }
    }

    // ---- epilogue: *gamma, write f32
    const int col_l = (lane & 3) * 2;
    const float* gptr = gamma + n0 + warp_n * 64;
    float gv0[8], gv1[8];
#pragma unroll
    for (int nj = 0; nj < 8; nj++) {
        gv0[nj] = __ldg(gptr + nj * 8 + col_l);
        gv1[nj] = __ldg(gptr + nj * 8 + col_l + 1);
    }

    const int row_base = m0 + warp_m * 64 + (lane >> 2);
#pragma unroll
    for (int mi = 0; mi < 4; mi++) {
        float* op0 = out + (size_t)(row_base + mi * 16) * DOUT + n0 + warp_n * 64;
        float* op1 = op0 + (size_t)8 * DOUT;
#pragma unroll
        for (int nj = 0; nj < 8; nj++) {
            float2 v0, v1;
            v0.x = acc[mi][nj][0] * gv0[nj];
            v0.y = acc[mi][nj][1] * gv1[nj];
            v1.x = acc[mi][nj][2] * gv0[nj];
            v1.y = acc[mi][nj][3] * gv1[nj];
            *reinterpret_cast<float2*>(op0 + nj * 8 + col_l) = v0;
            *reinterpret_cast<float2*>(op1 + nj * 8 + col_l) = v1;
        }
    }
}

// ------------------------------- launch --------------------------------------
extern "C" void kernel_launch(void* const* d_in, const int* in_sizes, int n_in,
                              void* d_out, int out_size) {
    const float* x     = (const float*)d_in[0];  // [2,4096,4096]
    const float* nw    = (const float*)d_in[1];  // [4096]
    const float* wq    = (const float*)d_in[2];  // [4096,4096]
    const float* gamma = (const float*)d_in[3];  // [4096]
    float* out = (float*)d_out;

    cudaFuncSetAttribute(bitlinear_gemm_kernel,
                         cudaFuncAttributeMaxDynamicSharedMemorySize, SMEM_SZ);

    rmsnorm_kernel<<<MROWS, 256>>>(x, nw);
    wconv_kernel<<<4096, 256>>>(wq);
    bitlinear_gemm_kernel<<<dim3(DOUT / BN, MROWS / BM), 256, SMEM_SZ>>>(gamma, out);
}

// round 5
// speedup vs baseline: 1.9079x; 1.0174x over previous
#include <cuda_runtime.h>
#include <cuda_fp16.h>
#include <cstdint>

// ----------------------------------------------------------------------------
// BitLinear: y = RMSNorm(x) @ w_q^T * gamma
// R1: harness PTX target is baseline sm_103 (no 'a') -> no tcgen05.
// R2: two-pass bf16 @1306us (over-precise). R3: fp16 single pass @773us.
// R4: 64x64 warp tile @697us (~11 cyc/HMMA vs ~8 floor).
// R5: double-buffered ldmatrix fragments -> hide LDSM latency under HMMAs.
// ----------------------------------------------------------------------------

#define DIN   4096
#define DOUT  4096
#define MROWS 8192

__device__ __align__(256) __half g_xn[(size_t)MROWS * DIN];
__device__ __align__(256) __half g_wq[(size_t)DOUT * DIN];

// ---------------------------- PTX helpers -----------------------------------
__device__ __forceinline__ uint32_t smem_u32(const void* p) {
    uint32_t a;
    asm("{ .reg .u64 t; cvta.to.shared.u64 t, %1; cvt.u32.u64 %0, t; }"
        : "=r"(a) : "l"(p));
    return a;
}

__device__ __forceinline__ void cp_async16(uint32_t dst, const void* src) {
    asm volatile("cp.async.cg.shared.global [%0], [%1], 16;"
                 :: "r"(dst), "l"(src));
}

#define CP_COMMIT() asm volatile("cp.async.commit_group;" ::: "memory")

#define LDSM_X4(r0, r1, r2, r3, addr) \
    asm volatile("ldmatrix.sync.aligned.m8n8.x4.shared.b16 {%0,%1,%2,%3}, [%4];" \
                 : "=r"(r0), "=r"(r1), "=r"(r2), "=r"(r3) : "r"(addr))

#define MMA16816(d, a, b0, b1) \
    asm volatile("mma.sync.aligned.m16n8k16.row.col.f32.f16.f16.f32 " \
                 "{%0,%1,%2,%3}, {%4,%5,%6,%7}, {%8,%9}, {%0,%1,%2,%3};" \
                 : "+f"((d)[0]), "+f"((d)[1]), "+f"((d)[2]), "+f"((d)[3]) \
                 : "r"((a)[0]), "r"((a)[1]), "r"((a)[2]), "r"((a)[3]), \
                   "r"(b0), "r"(b1))

// ----------------------------- GEMM config ----------------------------------
constexpr int BM = 128, BN = 256, BK = 64;
constexpr int KTILES = DIN / BK;               // 64
constexpr int STAGES = 4;
constexpr int TILE_A  = BM * BK * 2;           // 16384 B
constexpr int TILE_BB = BN * BK * 2;           // 32768 B
constexpr int STAGE_B = TILE_A + TILE_BB;      // 49152
constexpr int SMEM_SZ = STAGES * STAGE_B;      // 196608

// ------------------------ Kernel 1: RMSNorm -> fp16 --------------------------
__global__ __launch_bounds__(256) void rmsnorm_kernel(
    const float* __restrict__ x, const float* __restrict__ nw) {
    const int row = blockIdx.x;
    const float4* xr = reinterpret_cast<const float4*>(x) + (size_t)row * (DIN / 4);
    const float4* nw4 = reinterpret_cast<const float4*>(nw);
    const int t = threadIdx.x;

    float4 v[4];
    float ss = 0.f;
#pragma unroll
    for (int i = 0; i < 4; i++) {
        v[i] = xr[t + i * 256];
        ss += v[i].x * v[i].x + v[i].y * v[i].y + v[i].z * v[i].z + v[i].w * v[i].w;
    }
#pragma unroll
    for (int o = 16; o > 0; o >>= 1) ss += __shfl_xor_sync(0xffffffffu, ss, o);

    __shared__ float wss[8];
    __shared__ float s_scale;
    if ((t & 31) == 0) wss[t >> 5] = ss;
    __syncthreads();
    if (t == 0) {
        float tot = 0.f;
#pragma unroll
        for (int i = 0; i < 8; i++) tot += wss[i];
        s_scale = rsqrtf(tot * (1.0f / DIN) + 1e-6f);
    }
    __syncthreads();
    const float sc = s_scale;

    uint2* xo = reinterpret_cast<uint2*>(g_xn + (size_t)row * DIN);
#pragma unroll
    for (int i = 0; i < 4; i++) {
        float4 w = nw4[t + i * 256];
        __half2 h01 = __floats2half2_rn(v[i].x * sc * w.x, v[i].y * sc * w.y);
        __half2 h23 = __floats2half2_rn(v[i].z * sc * w.z, v[i].w * sc * w.w);
        uint2 u;
        u.x = *reinterpret_cast<uint32_t*>(&h01);
        u.y = *reinterpret_cast<uint32_t*>(&h23);
        xo[t + i * 256] = u;
    }
}

// ------------------------ Kernel 2: w_q fp32 -> fp16 --------------------------
__global__ __launch_bounds__(256) void wconv_kernel(const float* __restrict__ w) {
    const size_t gid = (size_t)blockIdx.x * 256 + threadIdx.x;
    const float4* w4 = reinterpret_cast<const float4*>(w);
    uint2* o = reinterpret_cast<uint2*>(g_wq);
#pragma unroll
    for (int i = 0; i < 4; i++) {
        size_t idx = gid + (size_t)i * 1048576;
        float4 v = w4[idx];
        __half2 h01 = __floats2half2_rn(v.x, v.y);
        __half2 h23 = __floats2half2_rn(v.z, v.w);
        uint2 u;
        u.x = *reinterpret_cast<uint32_t*>(&h01);
        u.y = *reinterpret_cast<uint32_t*>(&h23);
        o[idx] = u;
    }
}

// ------------------------ Kernel 3: HMMA GEMM --------------------------------
// 256 threads = 8 warps in a 2(m) x 4(n) grid; warp tile 64x64.
// Fragments double-buffered across kk-steps: LDSM(kk+1) issues before MMA(kk).
__global__ __launch_bounds__(256, 1)
void bitlinear_gemm_kernel(const float* __restrict__ gamma, float* __restrict__ out) {
    extern __shared__ char smem[];
    const uint32_t sb = smem_u32(smem);
    const int tid = threadIdx.x;
    const int wid = tid >> 5;
    const int lane = tid & 31;
    const int warp_m = wid >> 2;       // 0..1
    const int warp_n = wid & 3;        // 0..3
    const int m0 = blockIdx.y * BM;
    const int n0 = blockIdx.x * BN;

    // ---- per-thread copy geometry (16B chunks; 128B rows, XOR swizzle)
    const int cc = tid & 7;
    const int r0c = tid >> 3;
    const uint32_t so_base = (uint32_t)(r0c * 128 + ((cc ^ (r0c & 7)) << 4));
    const char* gA = (const char*)g_xn + (size_t)m0 * (DIN * 2);
    const char* gB = (const char*)g_wq + (size_t)n0 * (DIN * 2);
    const size_t grow0 = (size_t)r0c * (DIN * 2);

    auto issue_stage = [&](int s, int kt) {
        const uint32_t sdst = sb + (uint32_t)s * STAGE_B;
        const uint32_t koff = (uint32_t)kt * 128 + (uint32_t)cc * 16;
        const char* a = gA + grow0 + koff;
        const char* b = gB + grow0 + koff;
#pragma unroll
        for (int i = 0; i < 4; i++)
            cp_async16(sdst + so_base + i * (32 * 128),
                       a + (size_t)i * (32 * DIN * 2));
#pragma unroll
        for (int i = 0; i < 8; i++)
            cp_async16(sdst + TILE_A + so_base + i * (32 * 128),
                       b + (size_t)i * (32 * DIN * 2));
    };

    // ---- ldmatrix address components
    const int rA0 = warp_m * 64 + (lane & 15);
    const int cgA = lane >> 4;
    const int gB4 = lane >> 3;
    const int rB0 = warp_n * 64 + ((gB4 & 2) << 2) + (lane & 7);
    const int cgB = gB4 & 1;

    // Precompute swizzled per-kk offsets for the 8 fragment loads.
    // off = r*128 + (((kk*2+cg) ^ (r&7)) << 4); r fixed per slot.
    uint32_t offA[4][4], offB[4][4];   // [mi or p][kk]
#pragma unroll
    for (int kk = 0; kk < 4; kk++) {
#pragma unroll
        for (int mi = 0; mi < 4; mi++) {
            const int r = rA0 + mi * 16;
            offA[mi][kk] = (uint32_t)(r * 128 + (((kk * 2 + cgA) ^ (r & 7)) << 4));
        }
#pragma unroll
        for (int p = 0; p < 4; p++) {
            const int r = rB0 + p * 16;
            offB[p][kk] = (uint32_t)(r * 128 + (((kk * 2 + cgB) ^ (r & 7)) << 4))
                          + TILE_A;
        }
    }

    float acc[4][8][4];
#pragma unroll
    for (int mi = 0; mi < 4; mi++)
#pragma unroll
        for (int nj = 0; nj < 8; nj++)
#pragma unroll
            for (int e = 0; e < 4; e++) acc[mi][nj][e] = 0.f;

    uint32_t af[2][4][4], bf[2][4][4];   // double-buffered fragments

    auto load_frags = [&](int buf, uint32_t base, int kk) {
#pragma unroll
        for (int mi = 0; mi < 4; mi++)
            LDSM_X4(af[buf][mi][0], af[buf][mi][1], af[buf][mi][2],
                    af[buf][mi][3], base + offA[mi][kk]);
#pragma unroll
        for (int p = 0; p < 4; p++)
            LDSM_X4(bf[buf][p][0], bf[buf][p][1], bf[buf][p][2],
                    bf[buf][p][3], base + offB[p][kk]);
    };

    auto do_mma = [&](int buf) {
#pragma unroll
        for (int mi = 0; mi < 4; mi++)
#pragma unroll
            for (int p = 0; p < 4; p++) {
                MMA16816(acc[mi][2 * p],     af[buf][mi], bf[buf][p][0], bf[buf][p][1]);
                MMA16816(acc[mi][2 * p + 1], af[buf][mi], bf[buf][p][2], bf[buf][p][3]);
            }
    };

    // ---- prologue
#pragma unroll
    for (int s = 0; s < STAGES - 1; s++) { issue_stage(s, s); CP_COMMIT(); }

    // ---- main loop (fragment software pipeline inside each kt)
    for (int kt = 0; kt < KTILES; kt++) {
        asm volatile("cp.async.wait_group 2;" ::: "memory");
        __syncthreads();

        const int nk = kt + STAGES - 1;
        if (nk < KTILES) issue_stage(nk & (STAGES - 1), nk);
        CP_COMMIT();

        const uint32_t base = sb + (uint32_t)(kt & (STAGES - 1)) * STAGE_B;

        load_frags(0, base, 0);
#pragma unroll
        for (int kk = 0; kk < 4; kk++) {
            if (kk < 3) load_frags((kk + 1) & 1, base, kk + 1);
            do_mma(kk & 1);
        }
    }

    // ---- epilogue: *gamma, write f32
    const int col_l = (lane & 3) * 2;
    const float* gptr = gamma + n0 + warp_n * 64;
    float gv0[8], gv1[8];
#pragma unroll
    for (int nj = 0; nj < 8; nj++) {
        gv0[nj] = __ldg(gptr + nj * 8 + col_l);
        gv1[nj] = __ldg(gptr + nj * 8 + col_l + 1);
    }

    const int row_base = m0 + warp_m * 64 + (lane >> 2);
#pragma unroll
    for (int mi = 0; mi < 4; mi++) {
        float* op0 = out + (size_t)(row_base + mi * 16) * DOUT + n0 + warp_n * 64;
        float* op1 = op0 + (size_t)8 * DOUT;
#pragma unroll
        for (int nj = 0; nj < 8; nj++) {
            float2 v0, v1;
            v0.x = acc[mi][nj][0] * gv0[nj];
            v0.y = acc[mi][nj][1] * gv1[nj];
            v1.x = acc[mi][nj][2] * gv0[nj];
            v1.y = acc[mi][nj][3] * gv1[nj];
            *reinterpret_cast<float2*>(op0 + nj * 8 + col_l) = v0;
            *reinterpret_cast<float2*>(op1 + nj * 8 + col_l) = v1;
        }
    }
}

// ------------------------------- launch --------------------------------------
extern "C" void kernel_launch(void* const* d_in, const int* in_sizes, int n_in,
                              void* d_out, int out_size) {
    const float* x     = (const float*)d_in[0];  // [2,4096,4096]
    const float* nw    = (const float*)d_in[1];  // [4096]
    const float* wq    = (const float*)d_in[2];  // [4096,4096]
    const float* gamma = (const float*)d_in[3];  // [4096]
    float* out = (float*)d_out;

    cudaFuncSetAttribute(bitlinear_gemm_kernel,
                         cudaFuncAttributeMaxDynamicSharedMemorySize, SMEM_SZ);

    rmsnorm_kernel<<<MROWS, 256>>>(x, nw);
    wconv_kernel<<<4096, 256>>>(wq);
    bitlinear_gemm_kernel<<<dim3(DOUT / BN, MROWS / BM), 256, SMEM_SZ>>>(gamma, out);
}